// round 13
// baseline (speedup 1.0000x reference)
#include <cuda_runtime.h>
#include <cuda_bf16.h>
#include <cstdint>

// DiffAttention via mma.sync bf16 hi/lo-split.
// out[n,h,d] = sum_l sigmoid(q.k) * v / sum_l sigmoid(q.k);  N=L=4096, H=8, M=D=64.
// CTA = 64 query rows x 1 head (4 warps x 16 rows); loop over L in 64-row tiles.
// Small CTAs -> 4 independent CTAs/SM; their barrier phases stagger, so one
// CTA's staging/MUFU bubbles overlap another's MMA phase (R12 ran 2 big CTAs
// in near-lockstep at tensor=55%).
// S stays in registers between GEMM1 and GEMM2; Q A-frags persistent.

#define NN 4096
#define LL 4096
#define HH 8
#define MM 64
#define DD 64
#define BM 64
#define BL 64
#define NTHREADS 128
#define NITER (LL / BL)

// smem byte offsets, all rows 128B (64 bf16), SW128-swizzled
#define SQH 0            // Q hi 64x64 (8KB)
#define SQL 8192         // Q lo
#define SKH 16384        // K hi 64x64 [l][m] (8KB)
#define SKL 24576
#define SVH 32768        // V hi 64x64 [l][d] (8KB)
#define SVL 40960
#define SMEM_BYTES (49152 + 1024)

static __device__ __forceinline__ uint32_t smem_u32(const void* p) {
    uint32_t a;
    asm("{ .reg .u64 t; cvta.to.shared.u64 t, %1; cvt.u32.u64 %0, t; }" : "=r"(a) : "l"(p));
    return a;
}
static __device__ __forceinline__ uint32_t sw128(uint32_t off) {
    return off ^ ((off >> 3) & 0x70);
}
static __device__ __forceinline__ void ldmx4(uint32_t addr, uint32_t r[4]) {
    asm volatile("ldmatrix.sync.aligned.m8n8.x4.shared.b16 {%0,%1,%2,%3}, [%4];"
        : "=r"(r[0]), "=r"(r[1]), "=r"(r[2]), "=r"(r[3]) : "r"(addr));
}
static __device__ __forceinline__ void ldmx4t(uint32_t addr, uint32_t r[4]) {
    asm volatile("ldmatrix.sync.aligned.m8n8.x4.trans.shared.b16 {%0,%1,%2,%3}, [%4];"
        : "=r"(r[0]), "=r"(r[1]), "=r"(r[2]), "=r"(r[3]) : "r"(addr));
}
static __device__ __forceinline__ void mma16816(float d[4], const uint32_t a[4],
                                                uint32_t b0, uint32_t b1) {
    asm volatile(
        "mma.sync.aligned.m16n8k16.row.col.f32.bf16.bf16.f32 "
        "{%0,%1,%2,%3}, {%4,%5,%6,%7}, {%8,%9}, {%0,%1,%2,%3};"
        : "+f"(d[0]), "+f"(d[1]), "+f"(d[2]), "+f"(d[3])
        : "r"(a[0]), "r"(a[1]), "r"(a[2]), "r"(a[3]), "r"(b0), "r"(b1));
}

// split two floats into packed bf16x2 hi + bf16x2 lo (x ~= hi + lo)
static __device__ __forceinline__ void split2(float x0, float x1, uint32_t& hi, uint32_t& lo) {
    __nv_bfloat162 h2 = __floats2bfloat162_rn(x0, x1);
    float r0 = x0 - __bfloat162float(h2.x);
    float r1 = x1 - __bfloat162float(h2.y);
    __nv_bfloat162 l2 = __floats2bfloat162_rn(r0, r1);
    hi = *reinterpret_cast<uint32_t*>(&h2);
    lo = *reinterpret_cast<uint32_t*>(&l2);
}
// sigmoid(x) = 0.5*tanh(x/2) + 0.5 — single MUFU.TANH
static __device__ __forceinline__ float sigmoidf_fast(float x) {
    float t;
    asm("tanh.approx.f32 %0, %1;" : "=f"(t) : "f"(x * 0.5f));
    return fmaf(t, 0.5f, 0.5f);
}

__global__ __launch_bounds__(NTHREADS, 4)
void diffattn_hmma(const float* __restrict__ Q, const float* __restrict__ K,
                   const float* __restrict__ V, float* __restrict__ out)
{
    extern __shared__ char smem_raw[];
    char* sp = (char*)((((uintptr_t)smem_raw) + 1023) & ~(uintptr_t)1023);
    const uint32_t sb = smem_u32(sp);

    const int tid = threadIdx.x;
    const int wid = tid >> 5;
    const int lid = tid & 31;
    const int h  = blockIdx.x & (HH - 1);
    const int n0 = (blockIdx.x >> 3) * BM;
    const int mw = wid * 16;               // this warp's query-row block
    const int t4 = lid >> 3, r8 = lid & 7; // ldmatrix lane decomposition

    // ---- stage Q tile once: split to bf16 hi/lo, SW128-swizzled [row][m] ----
    // 64x64 floats = 1024 float4 over 128 threads = 8 rounds
    #pragma unroll
    for (int i = 0; i < 8; i++) {
        const int c = tid + i * NTHREADS;
        const int row = c >> 4, m4 = c & 15;
        const float4 t = *(const float4*)(Q + ((size_t)(n0 + row) * HH + h) * MM + m4 * 4);
        uint32_t h0, l0r, h1, l1r;
        split2(t.x, t.y, h0, l0r); split2(t.z, t.w, h1, l1r);
        const uint32_t off = sw128(row * 128 + m4 * 8);
        *(uint2*)(sp + SQH + off) = make_uint2(h0, h1);
        *(uint2*)(sp + SQL + off) = make_uint2(l0r, l1r);
    }
    __syncthreads();

    // ---- preload Q A-fragments (persistent): 4 k-steps x (hi,lo) ----
    uint32_t qh[4][4], ql[4][4];
    {
        #pragma unroll
        for (int k = 0; k < 4; k++) {
            const int row = mw + (t4 & 1) * 8 + r8;
            const int kc  = k * 16 + (t4 >> 1) * 8;
            const uint32_t off = sw128(row * 128 + kc * 2);
            ldmx4(sb + SQH + off, qh[k]);
            ldmx4(sb + SQL + off, ql[k]);
        }
    }

    float oacc[8][4];
    #pragma unroll
    for (int j = 0; j < 8; j++)
        #pragma unroll
        for (int i = 0; i < 4; i++) oacc[j][i] = 0.f;
    float normLo = 0.f, normHi = 0.f;

    for (int lt = 0; lt < NITER; lt++) {
        const int l0g = lt * BL;

        // ---- stage K tile [l][m] and V tile [l][d], bf16 hi/lo ----
        // issue all 16 LDG.128 first (MLP=16), then split+store
        {
            float4 kt[8], vt[8];
            #pragma unroll
            for (int i = 0; i < 8; i++) {
                const int c = tid + i * NTHREADS;
                const int row = c >> 4, m4 = c & 15;
                kt[i] = *(const float4*)(K + ((size_t)(l0g + row) * HH + h) * MM + m4 * 4);
            }
            #pragma unroll
            for (int i = 0; i < 8; i++) {
                const int c = tid + i * NTHREADS;
                const int row = c >> 4, d4 = c & 15;
                vt[i] = *(const float4*)(V + ((size_t)(l0g + row) * HH + h) * DD + d4 * 4);
            }
            #pragma unroll
            for (int i = 0; i < 8; i++) {
                const int c = tid + i * NTHREADS;
                const int row = c >> 4, m4 = c & 15;
                uint32_t h0, l0r, h1, l1r;
                split2(kt[i].x, kt[i].y, h0, l0r); split2(kt[i].z, kt[i].w, h1, l1r);
                const uint32_t off = sw128(row * 128 + m4 * 8);
                *(uint2*)(sp + SKH + off) = make_uint2(h0, h1);
                *(uint2*)(sp + SKL + off) = make_uint2(l0r, l1r);
            }
            #pragma unroll
            for (int i = 0; i < 8; i++) {
                const int c = tid + i * NTHREADS;
                const int row = c >> 4, d4 = c & 15;
                uint32_t h0, l0r, h1, l1r;
                split2(vt[i].x, vt[i].y, h0, l0r); split2(vt[i].z, vt[i].w, h1, l1r);
                const uint32_t off = sw128(row * 128 + d4 * 8);
                *(uint2*)(sp + SVH + off) = make_uint2(h0, h1);
                *(uint2*)(sp + SVL + off) = make_uint2(l0r, l1r);
            }
        }
        __syncthreads();

        // ---- GEMM1: S[16x64] = Q K^T (qh*kh + qh*kl + ql*kh) ----
        float sacc[8][4];
        #pragma unroll
        for (int j = 0; j < 8; j++)
            #pragma unroll
            for (int i = 0; i < 4; i++) sacc[j][i] = 0.f;

        #pragma unroll
        for (int p = 0; p < 4; p++) {          // n (l-col) pair: tiles 2p, 2p+1
            #pragma unroll
            for (int k = 0; k < 4; k++) {      // k (m) step
                const int nrow = p * 16 + (t4 >> 1) * 8 + r8;
                const int kc   = k * 16 + (t4 & 1) * 8;
                const uint32_t off = sw128(nrow * 128 + kc * 2);
                uint32_t bh[4], bl[4];
                ldmx4(sb + SKH + off, bh);
                ldmx4(sb + SKL + off, bl);
                mma16816(sacc[2*p],   qh[k], bh[0], bh[1]);
                mma16816(sacc[2*p+1], qh[k], bh[2], bh[3]);
                mma16816(sacc[2*p],   qh[k], bl[0], bl[1]);
                mma16816(sacc[2*p+1], qh[k], bl[2], bl[3]);
                mma16816(sacc[2*p],   ql[k], bh[0], bh[1]);
                mma16816(sacc[2*p+1], ql[k], bh[2], bh[3]);
            }
        }

        // ---- epilogue in registers: sigmoid, norm, split into GEMM2 A-frags ----
        uint32_t sh[4][4], sl[4][4];
        #pragma unroll
        for (int kk = 0; kk < 4; kk++) {
            float s0[4], s1[4];
            #pragma unroll
            for (int i = 0; i < 4; i++) {
                s0[i] = sigmoidf_fast(sacc[2*kk][i]);
                s1[i] = sigmoidf_fast(sacc[2*kk+1][i]);
            }
            normLo += (s0[0] + s0[1]) + (s1[0] + s1[1]);
            normHi += (s0[2] + s0[3]) + (s1[2] + s1[3]);
            split2(s0[0], s0[1], sh[kk][0], sl[kk][0]);
            split2(s0[2], s0[3], sh[kk][1], sl[kk][1]);
            split2(s1[0], s1[1], sh[kk][2], sl[kk][2]);
            split2(s1[2], s1[3], sh[kk][3], sl[kk][3]);
        }

        // ---- GEMM2: O[16x64] += S V (sh*vh + sh*vl + sl*vh) ----
        #pragma unroll
        for (int p = 0; p < 4; p++) {          // n (d-col) pair: tiles 2p, 2p+1
            #pragma unroll
            for (int kk = 0; kk < 4; kk++) {   // k (l) step
                const int lrow = kk * 16 + (t4 & 1) * 8 + r8;
                const int dc   = p * 16 + (t4 >> 1) * 8;
                const uint32_t off = sw128(lrow * 128 + dc * 2);
                uint32_t vh[4], vl[4];
                ldmx4t(sb + SVH + off, vh);
                ldmx4t(sb + SVL + off, vl);
                mma16816(oacc[2*p],   sh[kk], vh[0], vh[1]);
                mma16816(oacc[2*p+1], sh[kk], vh[2], vh[3]);
                mma16816(oacc[2*p],   sh[kk], vl[0], vl[1]);
                mma16816(oacc[2*p+1], sh[kk], vl[2], vl[3]);
                mma16816(oacc[2*p],   sl[kk], vh[0], vh[1]);
                mma16816(oacc[2*p+1], sl[kk], vh[2], vh[3]);
            }
        }
        __syncthreads();   // protect K/V tiles before next iteration overwrites
    }

    // ---- finalize: quad-reduce norm (lanes lid&~3 share a row), scale, store ----
    #pragma unroll
    for (int m = 1; m <= 2; m <<= 1) {
        normLo += __shfl_xor_sync(0xffffffffu, normLo, m);
        normHi += __shfl_xor_sync(0xffffffffu, normHi, m);
    }
    const float invLo = 1.0f / normLo;
    const float invHi = 1.0f / normHi;

    const int rowLo = n0 + mw + (lid >> 2);
    const int rowHi = rowLo + 8;
    const int cbase = (lid & 3) * 2;
    #pragma unroll
    for (int j = 0; j < 8; j++) {
        float2 lo = make_float2(oacc[j][0] * invLo, oacc[j][1] * invLo);
        float2 hi = make_float2(oacc[j][2] * invHi, oacc[j][3] * invHi);
        *(float2*)(out + ((size_t)rowLo * HH + h) * DD + j * 8 + cbase) = lo;
        *(float2*)(out + ((size_t)rowHi * HH + h) * DD + j * 8 + cbase) = hi;
    }
}

extern "C" void kernel_launch(void* const* d_in, const int* in_sizes, int n_in,
                              void* d_out, int out_size)
{
    const float* queries = (const float*)d_in[0];
    const float* keys    = (const float*)d_in[1];
    const float* values  = (const float*)d_in[2];
    float* out = (float*)d_out;

    cudaFuncSetAttribute(diffattn_hmma,
                         cudaFuncAttributeMaxDynamicSharedMemorySize, SMEM_BYTES);

    const dim3 grid((NN / BM) * HH);   // 64 * 8 = 512 CTAs
    diffattn_hmma<<<grid, NTHREADS, SMEM_BYTES>>>(queries, keys, values, out);
}

// round 14
// speedup vs baseline: 1.3804x; 1.3804x over previous
#include <cuda_runtime.h>
#include <cuda_fp16.h>
#include <cstdint>

// DiffAttention via mma.sync fp16 hi/lo-split (R12 structure, fp16 numerics).
// out[n,h,d] = sum_l sigmoid(q.k) * v / sum_l sigmoid(q.k);  N=L=4096, H=8, M=D=64.
// CTA = 128 query rows x 1 head; 8 warps x 16 rows; loop over L in 64-row tiles.
// fp16 (11-bit mantissa) instead of bf16: GEMM1 = 3 terms (qh*kh + qh*kl + ql*kh),
// GEMM2 = 2 terms only (sh*vh + sh*vl) — dropped sl*v term contributes ~2^-12
// relative, ~2.4e-4 on the output (threshold 1e-3). 160 MMA/warp/iter vs 192.

#define NN 4096
#define LL 4096
#define HH 8
#define MM 64
#define DD 64
#define BM 128
#define BL 64
#define NTHREADS 256
#define NITER (LL / BL)

// smem byte offsets, all rows 128B (64 fp16), SW128-swizzled
#define SQH 0            // Q hi 128x64 (16KB)
#define SQL 16384        // Q lo
#define SKH 32768        // K hi 64x64 [l][m] (8KB)
#define SKL 40960
#define SVH 49152        // V hi 64x64 [l][d] (8KB)
#define SVL 57344
#define SMEM_BYTES (65536 + 1024)

static __device__ __forceinline__ uint32_t smem_u32(const void* p) {
    uint32_t a;
    asm("{ .reg .u64 t; cvta.to.shared.u64 t, %1; cvt.u32.u64 %0, t; }" : "=r"(a) : "l"(p));
    return a;
}
static __device__ __forceinline__ uint32_t sw128(uint32_t off) {
    return off ^ ((off >> 3) & 0x70);
}
static __device__ __forceinline__ void ldmx4(uint32_t addr, uint32_t r[4]) {
    asm volatile("ldmatrix.sync.aligned.m8n8.x4.shared.b16 {%0,%1,%2,%3}, [%4];"
        : "=r"(r[0]), "=r"(r[1]), "=r"(r[2]), "=r"(r[3]) : "r"(addr));
}
static __device__ __forceinline__ void ldmx4t(uint32_t addr, uint32_t r[4]) {
    asm volatile("ldmatrix.sync.aligned.m8n8.x4.trans.shared.b16 {%0,%1,%2,%3}, [%4];"
        : "=r"(r[0]), "=r"(r[1]), "=r"(r[2]), "=r"(r[3]) : "r"(addr));
}
static __device__ __forceinline__ void mma16816(float d[4], const uint32_t a[4],
                                                uint32_t b0, uint32_t b1) {
    asm volatile(
        "mma.sync.aligned.m16n8k16.row.col.f32.f16.f16.f32 "
        "{%0,%1,%2,%3}, {%4,%5,%6,%7}, {%8,%9}, {%0,%1,%2,%3};"
        : "+f"(d[0]), "+f"(d[1]), "+f"(d[2]), "+f"(d[3])
        : "r"(a[0]), "r"(a[1]), "r"(a[2]), "r"(a[3]), "r"(b0), "r"(b1));
}

// split two floats into packed fp16x2 hi + fp16x2 lo (x ~= hi + lo, ~22-bit eff.)
static __device__ __forceinline__ void split2(float x0, float x1, uint32_t& hi, uint32_t& lo) {
    __half2 h2 = __floats2half2_rn(x0, x1);
    float r0 = x0 - __half2float(h2.x);
    float r1 = x1 - __half2float(h2.y);
    __half2 l2 = __floats2half2_rn(r0, r1);
    hi = *reinterpret_cast<uint32_t*>(&h2);
    lo = *reinterpret_cast<uint32_t*>(&l2);
}
// simple pack (no residual) — for S which only needs the hi term
static __device__ __forceinline__ uint32_t pack_h2(float x0, float x1) {
    __half2 h2 = __floats2half2_rn(x0, x1);
    return *reinterpret_cast<uint32_t*>(&h2);
}
// sigmoid(x) = 0.5*tanh(x/2) + 0.5 — single MUFU.TANH
static __device__ __forceinline__ float sigmoidf_fast(float x) {
    float t;
    asm("tanh.approx.f32 %0, %1;" : "=f"(t) : "f"(x * 0.5f));
    return fmaf(t, 0.5f, 0.5f);
}

__global__ __launch_bounds__(NTHREADS, 2)
void diffattn_hmma(const float* __restrict__ Q, const float* __restrict__ K,
                   const float* __restrict__ V, float* __restrict__ out)
{
    extern __shared__ char smem_raw[];
    char* sp = (char*)((((uintptr_t)smem_raw) + 1023) & ~(uintptr_t)1023);
    const uint32_t sb = smem_u32(sp);

    const int tid = threadIdx.x;
    const int wid = tid >> 5;
    const int lid = tid & 31;
    const int h  = blockIdx.x & (HH - 1);
    const int n0 = (blockIdx.x >> 3) * BM;
    const int mw = wid * 16;               // this warp's query-row block
    const int t4 = lid >> 3, r8 = lid & 7; // ldmatrix lane decomposition

    // ---- stage Q tile once: split to fp16 hi/lo, SW128-swizzled [row][m] ----
    #pragma unroll
    for (int i = 0; i < 8; i++) {
        const int c = tid + i * NTHREADS;
        const int row = c >> 4, m4 = c & 15;
        const float4 t = *(const float4*)(Q + ((size_t)(n0 + row) * HH + h) * MM + m4 * 4);
        uint32_t h0, l0r, h1, l1r;
        split2(t.x, t.y, h0, l0r); split2(t.z, t.w, h1, l1r);
        const uint32_t off = sw128(row * 128 + m4 * 8);
        *(uint2*)(sp + SQH + off) = make_uint2(h0, h1);
        *(uint2*)(sp + SQL + off) = make_uint2(l0r, l1r);
    }
    __syncthreads();

    // ---- preload Q A-fragments (persistent): 4 k-steps x (hi,lo) ----
    uint32_t qh[4][4], ql[4][4];
    {
        #pragma unroll
        for (int k = 0; k < 4; k++) {
            const int row = mw + (t4 & 1) * 8 + r8;
            const int kc  = k * 16 + (t4 >> 1) * 8;
            const uint32_t off = sw128(row * 128 + kc * 2);
            ldmx4(sb + SQH + off, qh[k]);
            ldmx4(sb + SQL + off, ql[k]);
        }
    }

    float oacc[8][4];
    #pragma unroll
    for (int j = 0; j < 8; j++)
        #pragma unroll
        for (int i = 0; i < 4; i++) oacc[j][i] = 0.f;
    float normLo = 0.f, normHi = 0.f;

    for (int lt = 0; lt < NITER; lt++) {
        const int l0g = lt * BL;

        // ---- stage K tile [l][m] and V tile [l][d], fp16 hi/lo ----
        // issue all 8 LDG.128 first (MLP=8), then split+store
        {
            float4 kt[4], vt[4];
            #pragma unroll
            for (int i = 0; i < 4; i++) {
                const int c = tid + i * NTHREADS;
                const int row = c >> 4, m4 = c & 15;
                kt[i] = *(const float4*)(K + ((size_t)(l0g + row) * HH + h) * MM + m4 * 4);
            }
            #pragma unroll
            for (int i = 0; i < 4; i++) {
                const int c = tid + i * NTHREADS;
                const int row = c >> 4, d4 = c & 15;
                vt[i] = *(const float4*)(V + ((size_t)(l0g + row) * HH + h) * DD + d4 * 4);
            }
            #pragma unroll
            for (int i = 0; i < 4; i++) {
                const int c = tid + i * NTHREADS;
                const int row = c >> 4, m4 = c & 15;
                uint32_t h0, l0r, h1, l1r;
                split2(kt[i].x, kt[i].y, h0, l0r); split2(kt[i].z, kt[i].w, h1, l1r);
                const uint32_t off = sw128(row * 128 + m4 * 8);
                *(uint2*)(sp + SKH + off) = make_uint2(h0, h1);
                *(uint2*)(sp + SKL + off) = make_uint2(l0r, l1r);
            }
            #pragma unroll
            for (int i = 0; i < 4; i++) {
                const int c = tid + i * NTHREADS;
                const int row = c >> 4, d4 = c & 15;
                uint32_t h0, l0r, h1, l1r;
                split2(vt[i].x, vt[i].y, h0, l0r); split2(vt[i].z, vt[i].w, h1, l1r);
                const uint32_t off = sw128(row * 128 + d4 * 8);
                *(uint2*)(sp + SVH + off) = make_uint2(h0, h1);
                *(uint2*)(sp + SVL + off) = make_uint2(l0r, l1r);
            }
        }
        __syncthreads();

        // ---- GEMM1: S[16x64] = Q K^T (qh*kh + qh*kl + ql*kh) ----
        float sacc[8][4];
        #pragma unroll
        for (int j = 0; j < 8; j++)
            #pragma unroll
            for (int i = 0; i < 4; i++) sacc[j][i] = 0.f;

        #pragma unroll
        for (int p = 0; p < 4; p++) {          // n (l-col) pair: tiles 2p, 2p+1
            #pragma unroll
            for (int k = 0; k < 4; k++) {      // k (m) step
                const int nrow = p * 16 + (t4 >> 1) * 8 + r8;
                const int kc   = k * 16 + (t4 & 1) * 8;
                const uint32_t off = sw128(nrow * 128 + kc * 2);
                uint32_t bh[4], bl[4];
                ldmx4(sb + SKH + off, bh);
                ldmx4(sb + SKL + off, bl);
                mma16816(sacc[2*p],   qh[k], bh[0], bh[1]);
                mma16816(sacc[2*p+1], qh[k], bh[2], bh[3]);
                mma16816(sacc[2*p],   qh[k], bl[0], bl[1]);
                mma16816(sacc[2*p+1], qh[k], bl[2], bl[3]);
                mma16816(sacc[2*p],   ql[k], bh[0], bh[1]);
                mma16816(sacc[2*p+1], ql[k], bh[2], bh[3]);
            }
        }

        // ---- epilogue in registers: sigmoid, norm, pack S to fp16 (hi only) ----
        uint32_t sh[4][4];
        #pragma unroll
        for (int kk = 0; kk < 4; kk++) {
            float s0[4], s1[4];
            #pragma unroll
            for (int i = 0; i < 4; i++) {
                s0[i] = sigmoidf_fast(sacc[2*kk][i]);
                s1[i] = sigmoidf_fast(sacc[2*kk+1][i]);
            }
            normLo += (s0[0] + s0[1]) + (s1[0] + s1[1]);
            normHi += (s0[2] + s0[3]) + (s1[2] + s1[3]);
            sh[kk][0] = pack_h2(s0[0], s0[1]);
            sh[kk][1] = pack_h2(s0[2], s0[3]);
            sh[kk][2] = pack_h2(s1[0], s1[1]);
            sh[kk][3] = pack_h2(s1[2], s1[3]);
        }

        // ---- GEMM2: O[16x64] += S V (sh*vh + sh*vl), 2 terms ----
        #pragma unroll
        for (int p = 0; p < 4; p++) {          // n (d-col) pair: tiles 2p, 2p+1
            #pragma unroll
            for (int kk = 0; kk < 4; kk++) {   // k (l) step
                const int lrow = kk * 16 + (t4 & 1) * 8 + r8;
                const int dc   = p * 16 + (t4 >> 1) * 8;
                const uint32_t off = sw128(lrow * 128 + dc * 2);
                uint32_t vh[4], vl[4];
                ldmx4t(sb + SVH + off, vh);
                ldmx4t(sb + SVL + off, vl);
                mma16816(oacc[2*p],   sh[kk], vh[0], vh[1]);
                mma16816(oacc[2*p+1], sh[kk], vh[2], vh[3]);
                mma16816(oacc[2*p],   sh[kk], vl[0], vl[1]);
                mma16816(oacc[2*p+1], sh[kk], vl[2], vl[3]);
            }
        }
        __syncthreads();   // protect K/V tiles before next iteration overwrites
    }

    // ---- finalize: quad-reduce norm (lanes lid&~3 share a row), scale, store ----
    #pragma unroll
    for (int m = 1; m <= 2; m <<= 1) {
        normLo += __shfl_xor_sync(0xffffffffu, normLo, m);
        normHi += __shfl_xor_sync(0xffffffffu, normHi, m);
    }
    const float invLo = 1.0f / normLo;
    const float invHi = 1.0f / normHi;

    const int rowLo = n0 + mw + (lid >> 2);
    const int rowHi = rowLo + 8;
    const int cbase = (lid & 3) * 2;
    #pragma unroll
    for (int j = 0; j < 8; j++) {
        float2 lo = make_float2(oacc[j][0] * invLo, oacc[j][1] * invLo);
        float2 hi = make_float2(oacc[j][2] * invHi, oacc[j][3] * invHi);
        *(float2*)(out + ((size_t)rowLo * HH + h) * DD + j * 8 + cbase) = lo;
        *(float2*)(out + ((size_t)rowHi * HH + h) * DD + j * 8 + cbase) = hi;
    }
}

extern "C" void kernel_launch(void* const* d_in, const int* in_sizes, int n_in,
                              void* d_out, int out_size)
{
    const float* queries = (const float*)d_in[0];
    const float* keys    = (const float*)d_in[1];
    const float* values  = (const float*)d_in[2];
    float* out = (float*)d_out;

    cudaFuncSetAttribute(diffattn_hmma,
                         cudaFuncAttributeMaxDynamicSharedMemorySize, SMEM_BYTES);

    const dim3 grid((NN / BM) * HH);   // 32 * 8 = 256 CTAs
    diffattn_hmma<<<grid, NTHREADS, SMEM_BYTES>>>(queries, keys, values, out);
}

// round 15
// speedup vs baseline: 1.5578x; 1.1286x over previous
#include <cuda_runtime.h>
#include <cuda_fp16.h>
#include <cstdint>

// DiffAttention via mma.sync fp16 hi/lo-split + pre-converted K/V + cp.async staging.
// out[n,h,d] = sum_l sigmoid(q.k) * v / sum_l sigmoid(q.k);  N=L=4096, H=8, M=D=64.
// Pre-pass kernels split K and V (f32 -> fp16 hi/lo) into __device__ scratch once;
// the mainloop stages tiles with cp.async.cg (double-buffered, one group in flight)
// so the tensor pipe never waits on LDG latency or conversion math.
// GEMM1 = 3 terms (qh*kh + qh*kl + ql*kh); GEMM2 = 2 terms (sh*vh + sh*vl).

#define NN 4096
#define LL 4096
#define HH 8
#define MM 64
#define DD 64
#define BM 128
#define BL 64
#define NTHREADS 256
#define NITER (LL / BL)

// ---- device scratch: K/V pre-converted to fp16 hi/lo, same [l][h][m] layout ----
#define KV_ELEMS (LL * HH * MM)
__device__ __half g_KH[KV_ELEMS];
__device__ __half g_KL[KV_ELEMS];
__device__ __half g_VH[KV_ELEMS];
__device__ __half g_VL[KV_ELEMS];

// smem byte offsets, all rows 128B (64 fp16), SW128-swizzled
#define SQH 0            // Q hi 128x64 (16KB)
#define SQL 16384        // Q lo
#define SKV 32768        // double-buffered: buf{KH 8K, KL 8K, VH 8K, VL 8K} x2 = 64KB
#define SMEM_BYTES (98304 + 1024)

static __device__ __forceinline__ uint32_t smem_u32(const void* p) {
    uint32_t a;
    asm("{ .reg .u64 t; cvta.to.shared.u64 t, %1; cvt.u32.u64 %0, t; }" : "=r"(a) : "l"(p));
    return a;
}
static __device__ __forceinline__ uint32_t sw128(uint32_t off) {
    return off ^ ((off >> 3) & 0x70);
}
static __device__ __forceinline__ void ldmx4(uint32_t addr, uint32_t r[4]) {
    asm volatile("ldmatrix.sync.aligned.m8n8.x4.shared.b16 {%0,%1,%2,%3}, [%4];"
        : "=r"(r[0]), "=r"(r[1]), "=r"(r[2]), "=r"(r[3]) : "r"(addr));
}
static __device__ __forceinline__ void ldmx4t(uint32_t addr, uint32_t r[4]) {
    asm volatile("ldmatrix.sync.aligned.m8n8.x4.trans.shared.b16 {%0,%1,%2,%3}, [%4];"
        : "=r"(r[0]), "=r"(r[1]), "=r"(r[2]), "=r"(r[3]) : "r"(addr));
}
static __device__ __forceinline__ void mma16816(float d[4], const uint32_t a[4],
                                                uint32_t b0, uint32_t b1) {
    asm volatile(
        "mma.sync.aligned.m16n8k16.row.col.f32.f16.f16.f32 "
        "{%0,%1,%2,%3}, {%4,%5,%6,%7}, {%8,%9}, {%0,%1,%2,%3};"
        : "+f"(d[0]), "+f"(d[1]), "+f"(d[2]), "+f"(d[3])
        : "r"(a[0]), "r"(a[1]), "r"(a[2]), "r"(a[3]), "r"(b0), "r"(b1));
}
#define CPASYNC(dst, src) \
    asm volatile("cp.async.cg.shared.global [%0], [%1], 16;" :: "r"(dst), "l"(src) : "memory")
#define CP_COMMIT() asm volatile("cp.async.commit_group;" ::: "memory")
#define CP_WAIT(n)  asm volatile("cp.async.wait_group %0;" :: "n"(n) : "memory")

// split two floats into packed fp16x2 hi + fp16x2 lo (x ~= hi + lo, ~22-bit eff.)
static __device__ __forceinline__ void split2(float x0, float x1, uint32_t& hi, uint32_t& lo) {
    __half2 h2 = __floats2half2_rn(x0, x1);
    float r0 = x0 - __half2float(h2.x);
    float r1 = x1 - __half2float(h2.y);
    __half2 l2 = __floats2half2_rn(r0, r1);
    hi = *reinterpret_cast<uint32_t*>(&h2);
    lo = *reinterpret_cast<uint32_t*>(&l2);
}
static __device__ __forceinline__ uint32_t pack_h2(float x0, float x1) {
    __half2 h2 = __floats2half2_rn(x0, x1);
    return *reinterpret_cast<uint32_t*>(&h2);
}
// sigmoid(x) = 0.5*tanh(x/2) + 0.5 — single MUFU.TANH
static __device__ __forceinline__ float sigmoidf_fast(float x) {
    float t;
    asm("tanh.approx.f32 %0, %1;" : "=f"(t) : "f"(x * 0.5f));
    return fmaf(t, 0.5f, 0.5f);
}

// ---- pre-pass: split f32 -> fp16 hi/lo (vectorized float4 -> 2x uint2) ----
__global__ void preconv_k(const float* __restrict__ src) {
    const int idx = blockIdx.x * blockDim.x + threadIdx.x;   // over float4s
    const float4 t = *(const float4*)(src + idx * 4);
    uint32_t h0, l0, h1, l1;
    split2(t.x, t.y, h0, l0); split2(t.z, t.w, h1, l1);
    *(uint2*)(g_KH + idx * 4) = make_uint2(h0, h1);
    *(uint2*)(g_KL + idx * 4) = make_uint2(l0, l1);
}
__global__ void preconv_v(const float* __restrict__ src) {
    const int idx = blockIdx.x * blockDim.x + threadIdx.x;
    const float4 t = *(const float4*)(src + idx * 4);
    uint32_t h0, l0, h1, l1;
    split2(t.x, t.y, h0, l0); split2(t.z, t.w, h1, l1);
    *(uint2*)(g_VH + idx * 4) = make_uint2(h0, h1);
    *(uint2*)(g_VL + idx * 4) = make_uint2(l0, l1);
}

// stage one 64-row K/V tile (all four fp16 parts) into buffer `buf` via cp.async
static __device__ __forceinline__ void stage_tile(uint32_t sb, int buf, int l0, int h, int tid) {
    const uint32_t kb = sb + SKV + buf * 32768;
    #pragma unroll
    for (int i = 0; i < 2; i++) {
        const int c = tid + i * NTHREADS;       // 0..511
        const int row = c >> 3, col = c & 7;    // 64 rows x 8 chunks of 16B
        const uint32_t soff = sw128(row * 128 + col * 16);
        const size_t g = ((size_t)(l0 + row) * HH + h) * MM + col * 8;
        CPASYNC(kb + soff,         g_KH + g);
        CPASYNC(kb + 8192 + soff,  g_KL + g);
        CPASYNC(kb + 16384 + soff, g_VH + g);
        CPASYNC(kb + 24576 + soff, g_VL + g);
    }
    CP_COMMIT();
}

__global__ __launch_bounds__(NTHREADS, 2)
void diffattn_hmma(const float* __restrict__ Q, float* __restrict__ out)
{
    extern __shared__ char smem_raw[];
    char* sp = (char*)((((uintptr_t)smem_raw) + 1023) & ~(uintptr_t)1023);
    const uint32_t sb = smem_u32(sp);

    const int tid = threadIdx.x;
    const int wid = tid >> 5;
    const int lid = tid & 31;
    const int h  = blockIdx.x & (HH - 1);
    const int n0 = (blockIdx.x >> 3) * BM;
    const int mw = wid * 16;               // this warp's query-row block
    const int t4 = lid >> 3, r8 = lid & 7; // ldmatrix lane decomposition

    // ---- prologue: start cp.async for tile 0 immediately ----
    stage_tile(sb, 0, 0, h, tid);

    // ---- stage Q tile once: split to fp16 hi/lo, SW128-swizzled [row][m] ----
    #pragma unroll
    for (int i = 0; i < 8; i++) {
        const int c = tid + i * NTHREADS;
        const int row = c >> 4, m4 = c & 15;
        const float4 t = *(const float4*)(Q + ((size_t)(n0 + row) * HH + h) * MM + m4 * 4);
        uint32_t h0, l0r, h1, l1r;
        split2(t.x, t.y, h0, l0r); split2(t.z, t.w, h1, l1r);
        const uint32_t off = sw128(row * 128 + m4 * 8);
        *(uint2*)(sp + SQH + off) = make_uint2(h0, h1);
        *(uint2*)(sp + SQL + off) = make_uint2(l0r, l1r);
    }
    __syncthreads();

    // ---- preload Q A-fragments (persistent): 4 k-steps x (hi,lo) ----
    uint32_t qh[4][4], ql[4][4];
    {
        #pragma unroll
        for (int k = 0; k < 4; k++) {
            const int row = mw + (t4 & 1) * 8 + r8;
            const int kc  = k * 16 + (t4 >> 1) * 8;
            const uint32_t off = sw128(row * 128 + kc * 2);
            ldmx4(sb + SQH + off, qh[k]);
            ldmx4(sb + SQL + off, ql[k]);
        }
    }

    float oacc[8][4];
    #pragma unroll
    for (int j = 0; j < 8; j++)
        #pragma unroll
        for (int i = 0; i < 4; i++) oacc[j][i] = 0.f;
    float normLo = 0.f, normHi = 0.f;

    for (int lt = 0; lt < NITER; lt++) {
        const int buf = lt & 1;
        const uint32_t kh_b = sb + SKV + buf * 32768;
        const uint32_t kl_b = kh_b + 8192;
        const uint32_t vh_b = kh_b + 16384;
        const uint32_t vl_b = kh_b + 24576;

        // issue next tile's copies, then wait for current tile's group
        if (lt + 1 < NITER) {
            stage_tile(sb, buf ^ 1, (lt + 1) * BL, h, tid);
            CP_WAIT(1);
        } else {
            CP_WAIT(0);
        }
        __syncthreads();   // all threads' copies for tile lt visible

        // ---- GEMM1: S[16x64] = Q K^T (qh*kh + qh*kl + ql*kh) ----
        float sacc[8][4];
        #pragma unroll
        for (int j = 0; j < 8; j++)
            #pragma unroll
            for (int i = 0; i < 4; i++) sacc[j][i] = 0.f;

        #pragma unroll
        for (int p = 0; p < 4; p++) {          // n (l-col) pair: tiles 2p, 2p+1
            #pragma unroll
            for (int k = 0; k < 4; k++) {      // k (m) step
                const int nrow = p * 16 + (t4 >> 1) * 8 + r8;
                const int kc   = k * 16 + (t4 & 1) * 8;
                const uint32_t off = sw128(nrow * 128 + kc * 2);
                uint32_t bh[4], bl[4];
                ldmx4(kh_b + off, bh);
                ldmx4(kl_b + off, bl);
                mma16816(sacc[2*p],   qh[k], bh[0], bh[1]);
                mma16816(sacc[2*p+1], qh[k], bh[2], bh[3]);
                mma16816(sacc[2*p],   qh[k], bl[0], bl[1]);
                mma16816(sacc[2*p+1], qh[k], bl[2], bl[3]);
                mma16816(sacc[2*p],   ql[k], bh[0], bh[1]);
                mma16816(sacc[2*p+1], ql[k], bh[2], bh[3]);
            }
        }

        // ---- epilogue in registers: sigmoid, norm, pack S to fp16 (hi only) ----
        uint32_t sh[4][4];
        #pragma unroll
        for (int kk = 0; kk < 4; kk++) {
            float s0[4], s1[4];
            #pragma unroll
            for (int i = 0; i < 4; i++) {
                s0[i] = sigmoidf_fast(sacc[2*kk][i]);
                s1[i] = sigmoidf_fast(sacc[2*kk+1][i]);
            }
            normLo += (s0[0] + s0[1]) + (s1[0] + s1[1]);
            normHi += (s0[2] + s0[3]) + (s1[2] + s1[3]);
            sh[kk][0] = pack_h2(s0[0], s0[1]);
            sh[kk][1] = pack_h2(s0[2], s0[3]);
            sh[kk][2] = pack_h2(s1[0], s1[1]);
            sh[kk][3] = pack_h2(s1[2], s1[3]);
        }

        // ---- GEMM2: O[16x64] += S V (sh*vh + sh*vl), 2 terms ----
        #pragma unroll
        for (int p = 0; p < 4; p++) {          // n (d-col) pair: tiles 2p, 2p+1
            #pragma unroll
            for (int kk = 0; kk < 4; kk++) {   // k (l) step
                const int lrow = kk * 16 + (t4 & 1) * 8 + r8;
                const int dc   = p * 16 + (t4 >> 1) * 8;
                const uint32_t off = sw128(lrow * 128 + dc * 2);
                uint32_t vh[4], vl[4];
                ldmx4t(vh_b + off, vh);
                ldmx4t(vl_b + off, vl);
                mma16816(oacc[2*p],   sh[kk], vh[0], vh[1]);
                mma16816(oacc[2*p+1], sh[kk], vh[2], vh[3]);
                mma16816(oacc[2*p],   sh[kk], vl[0], vl[1]);
                mma16816(oacc[2*p+1], sh[kk], vl[2], vl[3]);
            }
        }
        __syncthreads();   // all warps done with buf before next iter's stage into buf
    }

    // ---- finalize: quad-reduce norm (lanes lid&~3 share a row), scale, store ----
    #pragma unroll
    for (int m = 1; m <= 2; m <<= 1) {
        normLo += __shfl_xor_sync(0xffffffffu, normLo, m);
        normHi += __shfl_xor_sync(0xffffffffu, normHi, m);
    }
    const float invLo = 1.0f / normLo;
    const float invHi = 1.0f / normHi;

    const int rowLo = n0 + mw + (lid >> 2);
    const int rowHi = rowLo + 8;
    const int cbase = (lid & 3) * 2;
    #pragma unroll
    for (int j = 0; j < 8; j++) {
        float2 lo = make_float2(oacc[j][0] * invLo, oacc[j][1] * invLo);
        float2 hi = make_float2(oacc[j][2] * invHi, oacc[j][3] * invHi);
        *(float2*)(out + ((size_t)rowLo * HH + h) * DD + j * 8 + cbase) = lo;
        *(float2*)(out + ((size_t)rowHi * HH + h) * DD + j * 8 + cbase) = hi;
    }
}

extern "C" void kernel_launch(void* const* d_in, const int* in_sizes, int n_in,
                              void* d_out, int out_size)
{
    const float* queries = (const float*)d_in[0];
    const float* keys    = (const float*)d_in[1];
    const float* values  = (const float*)d_in[2];
    float* out = (float*)d_out;

    // pre-pass: split K and V into fp16 hi/lo scratch (KV_ELEMS/4 float4s each)
    preconv_k<<<KV_ELEMS / 4 / NTHREADS, NTHREADS>>>(keys);
    preconv_v<<<KV_ELEMS / 4 / NTHREADS, NTHREADS>>>(values);

    cudaFuncSetAttribute(diffattn_hmma,
                         cudaFuncAttributeMaxDynamicSharedMemorySize, SMEM_BYTES);
    const dim3 grid((NN / BM) * HH);   // 32 * 8 = 256 CTAs
    diffattn_hmma<<<grid, NTHREADS, SMEM_BYTES>>>(queries, out);
}

// round 16
// speedup vs baseline: 2.3460x; 1.5059x over previous
#include <cuda_runtime.h>
#include <cuda_fp16.h>
#include <cstdint>

// DiffAttention via mma.sync fp16 + selective hi/lo compensation + cp.async staging.
// out[n,h,d] = sum_l sigmoid(q.k) * v / sum_l sigmoid(q.k);  N=L=4096, H=8, M=D=64.
// Error-budgeted MMA reduction (calibrated against measured rel_err series):
//   GEMM1 = qh*kh + qh*kl   (Q plain fp16, K fp16 hi/lo — 2 terms)
//   GEMM2 = sh*vh           (S, V plain fp16 — 1 term)
// Predicted rel_err ~2.8e-4 vs 1e-3 threshold. 96 MMAs/warp/iter (was 160).
// K (hi/lo) and V (hi) pre-converted once into __device__ scratch; mainloop
// stages tiles with double-buffered cp.async.cg.

#define NN 4096
#define LL 4096
#define HH 8
#define MM 64
#define DD 64
#define BM 128
#define BL 64
#define NTHREADS 256
#define NITER (LL / BL)

// ---- device scratch: K fp16 hi/lo, V fp16 hi, same [l][h][m] layout ----
#define KV_ELEMS (LL * HH * MM)
__device__ __half g_KH[KV_ELEMS];
__device__ __half g_KL[KV_ELEMS];
__device__ __half g_VH[KV_ELEMS];

// smem byte offsets, all rows 128B (64 fp16), SW128-swizzled
#define SQH 0            // Q hi 128x64 (16KB)
#define SKV 16384        // double-buffered: buf{KH 8K, KL 8K, VH 8K} x2 = 48KB
#define BUFSTRIDE 24576
#define SMEM_BYTES (16384 + 49152 + 1024)

static __device__ __forceinline__ uint32_t smem_u32(const void* p) {
    uint32_t a;
    asm("{ .reg .u64 t; cvta.to.shared.u64 t, %1; cvt.u32.u64 %0, t; }" : "=r"(a) : "l"(p));
    return a;
}
static __device__ __forceinline__ uint32_t sw128(uint32_t off) {
    return off ^ ((off >> 3) & 0x70);
}
static __device__ __forceinline__ void ldmx4(uint32_t addr, uint32_t r[4]) {
    asm volatile("ldmatrix.sync.aligned.m8n8.x4.shared.b16 {%0,%1,%2,%3}, [%4];"
        : "=r"(r[0]), "=r"(r[1]), "=r"(r[2]), "=r"(r[3]) : "r"(addr));
}
static __device__ __forceinline__ void ldmx4t(uint32_t addr, uint32_t r[4]) {
    asm volatile("ldmatrix.sync.aligned.m8n8.x4.trans.shared.b16 {%0,%1,%2,%3}, [%4];"
        : "=r"(r[0]), "=r"(r[1]), "=r"(r[2]), "=r"(r[3]) : "r"(addr));
}
static __device__ __forceinline__ void mma16816(float d[4], const uint32_t a[4],
                                                uint32_t b0, uint32_t b1) {
    asm volatile(
        "mma.sync.aligned.m16n8k16.row.col.f32.f16.f16.f32 "
        "{%0,%1,%2,%3}, {%4,%5,%6,%7}, {%8,%9}, {%0,%1,%2,%3};"
        : "+f"(d[0]), "+f"(d[1]), "+f"(d[2]), "+f"(d[3])
        : "r"(a[0]), "r"(a[1]), "r"(a[2]), "r"(a[3]), "r"(b0), "r"(b1));
}
#define CPASYNC(dst, src) \
    asm volatile("cp.async.cg.shared.global [%0], [%1], 16;" :: "r"(dst), "l"(src) : "memory")
#define CP_COMMIT() asm volatile("cp.async.commit_group;" ::: "memory")
#define CP_WAIT(n)  asm volatile("cp.async.wait_group %0;" :: "n"(n) : "memory")

// split two floats into packed fp16x2 hi + fp16x2 lo (x ~= hi + lo)
static __device__ __forceinline__ void split2(float x0, float x1, uint32_t& hi, uint32_t& lo) {
    __half2 h2 = __floats2half2_rn(x0, x1);
    float r0 = x0 - __half2float(h2.x);
    float r1 = x1 - __half2float(h2.y);
    __half2 l2 = __floats2half2_rn(r0, r1);
    hi = *reinterpret_cast<uint32_t*>(&h2);
    lo = *reinterpret_cast<uint32_t*>(&l2);
}
static __device__ __forceinline__ uint32_t pack_h2(float x0, float x1) {
    __half2 h2 = __floats2half2_rn(x0, x1);
    return *reinterpret_cast<uint32_t*>(&h2);
}
// sigmoid(x) = 0.5*tanh(x/2) + 0.5 — single MUFU.TANH
static __device__ __forceinline__ float sigmoidf_fast(float x) {
    float t;
    asm("tanh.approx.f32 %0, %1;" : "=f"(t) : "f"(x * 0.5f));
    return fmaf(t, 0.5f, 0.5f);
}

// ---- pre-pass kernels ----
__global__ void preconv_k(const float* __restrict__ src) {
    const int idx = blockIdx.x * blockDim.x + threadIdx.x;   // over float4s
    const float4 t = *(const float4*)(src + idx * 4);
    uint32_t h0, l0, h1, l1;
    split2(t.x, t.y, h0, l0); split2(t.z, t.w, h1, l1);
    *(uint2*)(g_KH + idx * 4) = make_uint2(h0, h1);
    *(uint2*)(g_KL + idx * 4) = make_uint2(l0, l1);
}
__global__ void preconv_v(const float* __restrict__ src) {
    const int idx = blockIdx.x * blockDim.x + threadIdx.x;
    const float4 t = *(const float4*)(src + idx * 4);
    *(uint2*)(g_VH + idx * 4) = make_uint2(pack_h2(t.x, t.y), pack_h2(t.z, t.w));
}

// stage one 64-row K/V tile (KH, KL, VH) into buffer `buf` via cp.async
static __device__ __forceinline__ void stage_tile(uint32_t sb, int buf, int l0, int h, int tid) {
    const uint32_t kb = sb + SKV + buf * BUFSTRIDE;
    #pragma unroll
    for (int i = 0; i < 2; i++) {
        const int c = tid + i * NTHREADS;       // 0..511
        const int row = c >> 3, col = c & 7;    // 64 rows x 8 chunks of 16B
        const uint32_t soff = sw128(row * 128 + col * 16);
        const size_t g = ((size_t)(l0 + row) * HH + h) * MM + col * 8;
        CPASYNC(kb + soff,         g_KH + g);
        CPASYNC(kb + 8192 + soff,  g_KL + g);
        CPASYNC(kb + 16384 + soff, g_VH + g);
    }
    CP_COMMIT();
}

__global__ __launch_bounds__(NTHREADS, 2)
void diffattn_hmma(const float* __restrict__ Q, float* __restrict__ out)
{
    extern __shared__ char smem_raw[];
    char* sp = (char*)((((uintptr_t)smem_raw) + 1023) & ~(uintptr_t)1023);
    const uint32_t sb = smem_u32(sp);

    const int tid = threadIdx.x;
    const int wid = tid >> 5;
    const int lid = tid & 31;
    const int h  = blockIdx.x & (HH - 1);
    const int n0 = (blockIdx.x >> 3) * BM;
    const int mw = wid * 16;               // this warp's query-row block
    const int t4 = lid >> 3, r8 = lid & 7; // ldmatrix lane decomposition

    // ---- prologue: start cp.async for tile 0 immediately ----
    stage_tile(sb, 0, 0, h, tid);

    // ---- stage Q tile once: fp16 (hi only), SW128-swizzled [row][m] ----
    #pragma unroll
    for (int i = 0; i < 8; i++) {
        const int c = tid + i * NTHREADS;
        const int row = c >> 4, m4 = c & 15;
        const float4 t = *(const float4*)(Q + ((size_t)(n0 + row) * HH + h) * MM + m4 * 4);
        const uint32_t off = sw128(row * 128 + m4 * 8);
        *(uint2*)(sp + SQH + off) = make_uint2(pack_h2(t.x, t.y), pack_h2(t.z, t.w));
    }
    __syncthreads();

    // ---- preload Q A-fragments (persistent): 4 k-steps ----
    uint32_t qh[4][4];
    {
        #pragma unroll
        for (int k = 0; k < 4; k++) {
            const int row = mw + (t4 & 1) * 8 + r8;
            const int kc  = k * 16 + (t4 >> 1) * 8;
            const uint32_t off = sw128(row * 128 + kc * 2);
            ldmx4(sb + SQH + off, qh[k]);
        }
    }

    float oacc[8][4];
    #pragma unroll
    for (int j = 0; j < 8; j++)
        #pragma unroll
        for (int i = 0; i < 4; i++) oacc[j][i] = 0.f;
    float normLo = 0.f, normHi = 0.f;

    for (int lt = 0; lt < NITER; lt++) {
        const int buf = lt & 1;
        const uint32_t kh_b = sb + SKV + buf * BUFSTRIDE;
        const uint32_t kl_b = kh_b + 8192;
        const uint32_t vh_b = kh_b + 16384;

        // issue next tile's copies, then wait for current tile's group
        if (lt + 1 < NITER) {
            stage_tile(sb, buf ^ 1, (lt + 1) * BL, h, tid);
            CP_WAIT(1);
        } else {
            CP_WAIT(0);
        }
        __syncthreads();   // all threads' copies for tile lt visible

        // ---- GEMM1: S[16x64] = Q K^T (qh*kh + qh*kl) ----
        float sacc[8][4];
        #pragma unroll
        for (int j = 0; j < 8; j++)
            #pragma unroll
            for (int i = 0; i < 4; i++) sacc[j][i] = 0.f;

        #pragma unroll
        for (int p = 0; p < 4; p++) {          // n (l-col) pair: tiles 2p, 2p+1
            #pragma unroll
            for (int k = 0; k < 4; k++) {      // k (m) step
                const int nrow = p * 16 + (t4 >> 1) * 8 + r8;
                const int kc   = k * 16 + (t4 & 1) * 8;
                const uint32_t off = sw128(nrow * 128 + kc * 2);
                uint32_t bh[4], bl[4];
                ldmx4(kh_b + off, bh);
                ldmx4(kl_b + off, bl);
                mma16816(sacc[2*p],   qh[k], bh[0], bh[1]);
                mma16816(sacc[2*p+1], qh[k], bh[2], bh[3]);
                mma16816(sacc[2*p],   qh[k], bl[0], bl[1]);
                mma16816(sacc[2*p+1], qh[k], bl[2], bl[3]);
            }
        }

        // ---- epilogue in registers: sigmoid, norm, pack S to fp16 ----
        uint32_t sh[4][4];
        #pragma unroll
        for (int kk = 0; kk < 4; kk++) {
            float s0[4], s1[4];
            #pragma unroll
            for (int i = 0; i < 4; i++) {
                s0[i] = sigmoidf_fast(sacc[2*kk][i]);
                s1[i] = sigmoidf_fast(sacc[2*kk+1][i]);
            }
            normLo += (s0[0] + s0[1]) + (s1[0] + s1[1]);
            normHi += (s0[2] + s0[3]) + (s1[2] + s1[3]);
            sh[kk][0] = pack_h2(s0[0], s0[1]);
            sh[kk][1] = pack_h2(s0[2], s0[3]);
            sh[kk][2] = pack_h2(s1[0], s1[1]);
            sh[kk][3] = pack_h2(s1[2], s1[3]);
        }

        // ---- GEMM2: O[16x64] += S V (sh*vh, 1 term) ----
        #pragma unroll
        for (int p = 0; p < 4; p++) {          // n (d-col) pair: tiles 2p, 2p+1
            #pragma unroll
            for (int kk = 0; kk < 4; kk++) {   // k (l) step
                const int lrow = kk * 16 + (t4 & 1) * 8 + r8;
                const int dc   = p * 16 + (t4 >> 1) * 8;
                const uint32_t off = sw128(lrow * 128 + dc * 2);
                uint32_t vh[4];
                ldmx4t(vh_b + off, vh);
                mma16816(oacc[2*p],   sh[kk], vh[0], vh[1]);
                mma16816(oacc[2*p+1], sh[kk], vh[2], vh[3]);
            }
        }
        __syncthreads();   // all warps done with buf before next iter's stage into buf
    }

    // ---- finalize: quad-reduce norm (lanes lid&~3 share a row), scale, store ----
    #pragma unroll
    for (int m = 1; m <= 2; m <<= 1) {
        normLo += __shfl_xor_sync(0xffffffffu, normLo, m);
        normHi += __shfl_xor_sync(0xffffffffu, normHi, m);
    }
    const float invLo = 1.0f / normLo;
    const float invHi = 1.0f / normHi;

    const int rowLo = n0 + mw + (lid >> 2);
    const int rowHi = rowLo + 8;
    const int cbase = (lid & 3) * 2;
    #pragma unroll
    for (int j = 0; j < 8; j++) {
        float2 lo = make_float2(oacc[j][0] * invLo, oacc[j][1] * invLo);
        float2 hi = make_float2(oacc[j][2] * invHi, oacc[j][3] * invHi);
        *(float2*)(out + ((size_t)rowLo * HH + h) * DD + j * 8 + cbase) = lo;
        *(float2*)(out + ((size_t)rowHi * HH + h) * DD + j * 8 + cbase) = hi;
    }
}

extern "C" void kernel_launch(void* const* d_in, const int* in_sizes, int n_in,
                              void* d_out, int out_size)
{
    const float* queries = (const float*)d_in[0];
    const float* keys    = (const float*)d_in[1];
    const float* values  = (const float*)d_in[2];
    float* out = (float*)d_out;

    // pre-pass: K -> fp16 hi/lo, V -> fp16 hi (KV_ELEMS/4 float4s each)
    preconv_k<<<KV_ELEMS / 4 / NTHREADS, NTHREADS>>>(keys);
    preconv_v<<<KV_ELEMS / 4 / NTHREADS, NTHREADS>>>(values);

    cudaFuncSetAttribute(diffattn_hmma,
                         cudaFuncAttributeMaxDynamicSharedMemorySize, SMEM_BYTES);
    const dim3 grid((NN / BM) * HH);   // 32 * 8 = 256 CTAs
    diffattn_hmma<<<grid, NTHREADS, SMEM_BYTES>>>(queries, out);
}

// round 17
// speedup vs baseline: 3.0202x; 1.2874x over previous
#include <cuda_runtime.h>
#include <cuda_fp16.h>
#include <cstdint>

// DiffAttention via plain-fp16 mma.sync + cp.async staging.
// out[n,h,d] = sum_l sigmoid(q.k) * v / sum_l sigmoid(q.k);  N=L=4096, H=8, M=D=64.
// Error budget fully spent (calibrated over R14-R16 measured rel_err series):
//   GEMM1 = qh*kh  (plain fp16)     GEMM2 = sh*vh  (plain fp16)
// Predicted rel_err ~4e-4 vs 1e-3 threshold. 64 MMAs/warp/iter (was 96).
// K/V pre-converted to fp16 once; mainloop stages tiles with double-buffered
// cp.async.cg so the tensor pipe never waits on LDG latency or conversion.

#define NN 4096
#define LL 4096
#define HH 8
#define MM 64
#define DD 64
#define BM 128
#define BL 64
#define NTHREADS 256
#define NITER (LL / BL)

// ---- device scratch: K, V as fp16, same [l][h][m] layout ----
#define KV_ELEMS (LL * HH * MM)
__device__ __half g_KH[KV_ELEMS];
__device__ __half g_VH[KV_ELEMS];

// smem byte offsets, all rows 128B (64 fp16), SW128-swizzled
#define SQH 0            // Q 128x64 fp16 (16KB)
#define SKV 16384        // double-buffered: buf{KH 8K, VH 8K} x2 = 32KB
#define BUFSTRIDE 16384
#define SMEM_BYTES (16384 + 32768 + 1024)

static __device__ __forceinline__ uint32_t smem_u32(const void* p) {
    uint32_t a;
    asm("{ .reg .u64 t; cvta.to.shared.u64 t, %1; cvt.u32.u64 %0, t; }" : "=r"(a) : "l"(p));
    return a;
}
static __device__ __forceinline__ uint32_t sw128(uint32_t off) {
    return off ^ ((off >> 3) & 0x70);
}
static __device__ __forceinline__ void ldmx4(uint32_t addr, uint32_t r[4]) {
    asm volatile("ldmatrix.sync.aligned.m8n8.x4.shared.b16 {%0,%1,%2,%3}, [%4];"
        : "=r"(r[0]), "=r"(r[1]), "=r"(r[2]), "=r"(r[3]) : "r"(addr));
}
static __device__ __forceinline__ void ldmx4t(uint32_t addr, uint32_t r[4]) {
    asm volatile("ldmatrix.sync.aligned.m8n8.x4.trans.shared.b16 {%0,%1,%2,%3}, [%4];"
        : "=r"(r[0]), "=r"(r[1]), "=r"(r[2]), "=r"(r[3]) : "r"(addr));
}
static __device__ __forceinline__ void mma16816(float d[4], const uint32_t a[4],
                                                uint32_t b0, uint32_t b1) {
    asm volatile(
        "mma.sync.aligned.m16n8k16.row.col.f32.f16.f16.f32 "
        "{%0,%1,%2,%3}, {%4,%5,%6,%7}, {%8,%9}, {%0,%1,%2,%3};"
        : "+f"(d[0]), "+f"(d[1]), "+f"(d[2]), "+f"(d[3])
        : "r"(a[0]), "r"(a[1]), "r"(a[2]), "r"(a[3]), "r"(b0), "r"(b1));
}
#define CPASYNC(dst, src) \
    asm volatile("cp.async.cg.shared.global [%0], [%1], 16;" :: "r"(dst), "l"(src) : "memory")
#define CP_COMMIT() asm volatile("cp.async.commit_group;" ::: "memory")
#define CP_WAIT(n)  asm volatile("cp.async.wait_group %0;" :: "n"(n) : "memory")

static __device__ __forceinline__ uint32_t pack_h2(float x0, float x1) {
    __half2 h2 = __floats2half2_rn(x0, x1);
    return *reinterpret_cast<uint32_t*>(&h2);
}
// sigmoid(x) = 0.5*tanh(x/2) + 0.5 — single MUFU.TANH
static __device__ __forceinline__ float sigmoidf_fast(float x) {
    float t;
    asm("tanh.approx.f32 %0, %1;" : "=f"(t) : "f"(x * 0.5f));
    return fmaf(t, 0.5f, 0.5f);
}

// ---- pre-pass kernels: f32 -> fp16 ----
__global__ void preconv_k(const float* __restrict__ src) {
    const int idx = blockIdx.x * blockDim.x + threadIdx.x;   // over float4s
    const float4 t = *(const float4*)(src + idx * 4);
    *(uint2*)(g_KH + idx * 4) = make_uint2(pack_h2(t.x, t.y), pack_h2(t.z, t.w));
}
__global__ void preconv_v(const float* __restrict__ src) {
    const int idx = blockIdx.x * blockDim.x + threadIdx.x;
    const float4 t = *(const float4*)(src + idx * 4);
    *(uint2*)(g_VH + idx * 4) = make_uint2(pack_h2(t.x, t.y), pack_h2(t.z, t.w));
}

// stage one 64-row K/V tile (KH, VH) into buffer `buf` via cp.async
static __device__ __forceinline__ void stage_tile(uint32_t sb, int buf, int l0, int h, int tid) {
    const uint32_t kb = sb + SKV + buf * BUFSTRIDE;
    #pragma unroll
    for (int i = 0; i < 2; i++) {
        const int c = tid + i * NTHREADS;       // 0..511
        const int row = c >> 3, col = c & 7;    // 64 rows x 8 chunks of 16B
        const uint32_t soff = sw128(row * 128 + col * 16);
        const size_t g = ((size_t)(l0 + row) * HH + h) * MM + col * 8;
        CPASYNC(kb + soff,        g_KH + g);
        CPASYNC(kb + 8192 + soff, g_VH + g);
    }
    CP_COMMIT();
}

__global__ __launch_bounds__(NTHREADS, 2)
void diffattn_hmma(const float* __restrict__ Q, float* __restrict__ out)
{
    extern __shared__ char smem_raw[];
    char* sp = (char*)((((uintptr_t)smem_raw) + 1023) & ~(uintptr_t)1023);
    const uint32_t sb = smem_u32(sp);

    const int tid = threadIdx.x;
    const int wid = tid >> 5;
    const int lid = tid & 31;
    const int h  = blockIdx.x & (HH - 1);
    const int n0 = (blockIdx.x >> 3) * BM;
    const int mw = wid * 16;               // this warp's query-row block
    const int t4 = lid >> 3, r8 = lid & 7; // ldmatrix lane decomposition

    // ---- prologue: start cp.async for tile 0 immediately ----
    stage_tile(sb, 0, 0, h, tid);

    // ---- stage Q tile once: fp16, SW128-swizzled [row][m] ----
    #pragma unroll
    for (int i = 0; i < 8; i++) {
        const int c = tid + i * NTHREADS;
        const int row = c >> 4, m4 = c & 15;
        const float4 t = *(const float4*)(Q + ((size_t)(n0 + row) * HH + h) * MM + m4 * 4);
        const uint32_t off = sw128(row * 128 + m4 * 8);
        *(uint2*)(sp + SQH + off) = make_uint2(pack_h2(t.x, t.y), pack_h2(t.z, t.w));
    }
    __syncthreads();

    // ---- preload Q A-fragments (persistent): 4 k-steps ----
    uint32_t qh[4][4];
    {
        #pragma unroll
        for (int k = 0; k < 4; k++) {
            const int row = mw + (t4 & 1) * 8 + r8;
            const int kc  = k * 16 + (t4 >> 1) * 8;
            const uint32_t off = sw128(row * 128 + kc * 2);
            ldmx4(sb + SQH + off, qh[k]);
        }
    }

    float oacc[8][4];
    #pragma unroll
    for (int j = 0; j < 8; j++)
        #pragma unroll
        for (int i = 0; i < 4; i++) oacc[j][i] = 0.f;
    float normLo = 0.f, normHi = 0.f;

    for (int lt = 0; lt < NITER; lt++) {
        const int buf = lt & 1;
        const uint32_t kh_b = sb + SKV + buf * BUFSTRIDE;
        const uint32_t vh_b = kh_b + 8192;

        // issue next tile's copies, then wait for current tile's group
        if (lt + 1 < NITER) {
            stage_tile(sb, buf ^ 1, (lt + 1) * BL, h, tid);
            CP_WAIT(1);
        } else {
            CP_WAIT(0);
        }
        __syncthreads();   // all threads' copies for tile lt visible

        // ---- GEMM1: S[16x64] = Q K^T (qh*kh) ----
        float sacc[8][4];
        #pragma unroll
        for (int j = 0; j < 8; j++)
            #pragma unroll
            for (int i = 0; i < 4; i++) sacc[j][i] = 0.f;

        #pragma unroll
        for (int p = 0; p < 4; p++) {          // n (l-col) pair: tiles 2p, 2p+1
            #pragma unroll
            for (int k = 0; k < 4; k++) {      // k (m) step
                const int nrow = p * 16 + (t4 >> 1) * 8 + r8;
                const int kc   = k * 16 + (t4 & 1) * 8;
                const uint32_t off = sw128(nrow * 128 + kc * 2);
                uint32_t bh[4];
                ldmx4(kh_b + off, bh);
                mma16816(sacc[2*p],   qh[k], bh[0], bh[1]);
                mma16816(sacc[2*p+1], qh[k], bh[2], bh[3]);
            }
        }

        // ---- epilogue in registers: sigmoid, norm, pack S to fp16 ----
        uint32_t sh[4][4];
        #pragma unroll
        for (int kk = 0; kk < 4; kk++) {
            float s0[4], s1[4];
            #pragma unroll
            for (int i = 0; i < 4; i++) {
                s0[i] = sigmoidf_fast(sacc[2*kk][i]);
                s1[i] = sigmoidf_fast(sacc[2*kk+1][i]);
            }
            normLo += (s0[0] + s0[1]) + (s1[0] + s1[1]);
            normHi += (s0[2] + s0[3]) + (s1[2] + s1[3]);
            sh[kk][0] = pack_h2(s0[0], s0[1]);
            sh[kk][1] = pack_h2(s0[2], s0[3]);
            sh[kk][2] = pack_h2(s1[0], s1[1]);
            sh[kk][3] = pack_h2(s1[2], s1[3]);
        }

        // ---- GEMM2: O[16x64] += S V (sh*vh) ----
        #pragma unroll
        for (int p = 0; p < 4; p++) {          // n (d-col) pair: tiles 2p, 2p+1
            #pragma unroll
            for (int kk = 0; kk < 4; kk++) {   // k (l) step
                const int lrow = kk * 16 + (t4 & 1) * 8 + r8;
                const int dc   = p * 16 + (t4 >> 1) * 8;
                const uint32_t off = sw128(lrow * 128 + dc * 2);
                uint32_t vh[4];
                ldmx4t(vh_b + off, vh);
                mma16816(oacc[2*p],   sh[kk], vh[0], vh[1]);
                mma16816(oacc[2*p+1], sh[kk], vh[2], vh[3]);
            }
        }
        __syncthreads();   // all warps done with buf before next iter's stage into buf
    }

    // ---- finalize: quad-reduce norm (lanes lid&~3 share a row), scale, store ----
    #pragma unroll
    for (int m = 1; m <= 2; m <<= 1) {
        normLo += __shfl_xor_sync(0xffffffffu, normLo, m);
        normHi += __shfl_xor_sync(0xffffffffu, normHi, m);
    }
    const float invLo = 1.0f / normLo;
    const float invHi = 1.0f / normHi;

    const int rowLo = n0 + mw + (lid >> 2);
    const int rowHi = rowLo + 8;
    const int cbase = (lid & 3) * 2;
    #pragma unroll
    for (int j = 0; j < 8; j++) {
        float2 lo = make_float2(oacc[j][0] * invLo, oacc[j][1] * invLo);
        float2 hi = make_float2(oacc[j][2] * invHi, oacc[j][3] * invHi);
        *(float2*)(out + ((size_t)rowLo * HH + h) * DD + j * 8 + cbase) = lo;
        *(float2*)(out + ((size_t)rowHi * HH + h) * DD + j * 8 + cbase) = hi;
    }
}

extern "C" void kernel_launch(void* const* d_in, const int* in_sizes, int n_in,
                              void* d_out, int out_size)
{
    const float* queries = (const float*)d_in[0];
    const float* keys    = (const float*)d_in[1];
    const float* values  = (const float*)d_in[2];
    float* out = (float*)d_out;

    // pre-pass: K, V -> fp16 (KV_ELEMS/4 float4s each)
    preconv_k<<<KV_ELEMS / 4 / NTHREADS, NTHREADS>>>(keys);
    preconv_v<<<KV_ELEMS / 4 / NTHREADS, NTHREADS>>>(values);

    cudaFuncSetAttribute(diffattn_hmma,
                         cudaFuncAttributeMaxDynamicSharedMemorySize, SMEM_BYTES);
    const dim3 grid((NN / BM) * HH);   // 32 * 8 = 256 CTAs
    diffattn_hmma<<<grid, NTHREADS, SMEM_BYTES>>>(queries, out);
}